// round 16
// baseline (speedup 1.0000x reference)
#include <cuda_runtime.h>
#include <cuda_bf16.h>
#include <cstdint>

// ---------------- problem constants ----------------
#define MAX_N 50000
#define MAX_E 800000
#define D 128
#define CAP 64          // bucket slots per node (deg ~ Poisson(16); P(>=64) ~ 2e-18)

// ---------------- device-global scratch ----------------
__device__ int g_cursor[MAX_N];
__device__ int g_bucket[(size_t)MAX_N * CAP];
// bf16 hi/lo feature planes, each [node][64] u32 (= 128 bf16 per row, 256B)
__device__ __align__(128) uint32_t g_xh[(size_t)MAX_N * 64];
__device__ __align__(128) uint32_t g_xl[(size_t)MAX_N * 64];
__device__ __align__(128) uint32_t g_ah[(size_t)MAX_N * 64];
__device__ __align__(128) uint32_t g_al[(size_t)MAX_N * 64];
__device__ __align__(128) uint32_t g_hh[(size_t)MAX_N * 64];
__device__ __align__(128) uint32_t g_hl[(size_t)MAX_N * 64];
// bf16 hi/lo weight images, transposed: [layer][chunk(8)][n=128][k=32]
__device__ __align__(128) __nv_bfloat16 g_Bh[2][8][128 * 32];
__device__ __align__(128) __nv_bfloat16 g_Bl[2][8][128 * 32];

// ---------------- small helpers ----------------
__device__ __forceinline__ uint32_t pack_bf2(float a, float b) {
    __nv_bfloat162 t;
    t.x = __float2bfloat16(a);
    t.y = __float2bfloat16(b);
    return *reinterpret_cast<uint32_t*>(&t);
}
__device__ __forceinline__ float bf_res(float v) {
    return v - __bfloat162float(__float2bfloat16(v));
}
// packed f32x2 accumulate: acc += {lo_bits, hi_bits} viewed as 2 floats
__device__ __forceinline__ void fadd2(uint64_t& acc, uint32_t f0, uint32_t f1) {
    uint64_t v;
    asm("mov.b64 %0, {%1, %2};" : "=l"(v) : "r"(f0), "r"(f1));
    asm("add.rn.f32x2 %0, %0, %1;" : "+l"(acc) : "l"(v));
}
__device__ __forceinline__ void unpack2(uint64_t acc, float& a, float& b) {
    uint32_t u0, u1;
    asm("mov.b64 {%0, %1}, %2;" : "=r"(u0), "=r"(u1) : "l"(acc));
    a = __uint_as_float(u0);
    b = __uint_as_float(u1);
}

__device__ __forceinline__ uint32_t smem_u32(const void* p) {
    uint32_t a;
    asm("{ .reg .u64 t; cvta.to.shared.u64 t, %1; cvt.u32.u64 %0, t; }" : "=r"(a) : "l"(p));
    return a;
}
__device__ __forceinline__ void ldm_x4(uint32_t* r, uint32_t addr) {
    asm volatile("ldmatrix.sync.aligned.m8n8.x4.shared.b16 {%0,%1,%2,%3}, [%4];"
                 : "=r"(r[0]), "=r"(r[1]), "=r"(r[2]), "=r"(r[3]) : "r"(addr));
}
__device__ __forceinline__ void mma16816(float* d, const uint32_t* a, uint32_t b0, uint32_t b1) {
    asm volatile("mma.sync.aligned.m16n8k16.row.col.f32.bf16.bf16.f32 "
                 "{%0,%1,%2,%3}, {%4,%5,%6,%7}, {%8,%9}, {%0,%1,%2,%3};"
                 : "+f"(d[0]), "+f"(d[1]), "+f"(d[2]), "+f"(d[3])
                 : "r"(a[0]), "r"(a[1]), "r"(a[2]), "r"(a[3]), "r"(b0), "r"(b1));
}
__device__ __forceinline__ void cp16(uint32_t dst, const void* src, uint32_t sz) {
    asm volatile("cp.async.cg.shared.global [%0], [%1], 16, %2;"
                 :: "r"(dst), "l"(src), "r"(sz) : "memory");
}
#define CP_COMMIT()  asm volatile("cp.async.commit_group;" ::: "memory")
#define CP_WAIT(N)   asm volatile("cp.async.wait_group %0;" :: "n"(N) : "memory")

// XOR swizzle: 64B rows, 4x16B chunks; conflict-free for ldmatrix
#define SWZ(row, ci) (((uint32_t)(row) << 6) + (((((ci) ^ ((row) >> 1)) & 3)) << 4))

// ---------------- graph build: single-pass bucket scatter ----------------
__global__ void k_scatter(const int* __restrict__ ei, int E2, int n) {
    int t = blockIdx.x * blockDim.x + threadIdx.x;   // handles 2 edges
    if (t < E2) {
        int2 sp = ((const int2*)ei)[t];
        int2 dp = ((const int2*)(ei + 2 * E2))[t];
        int d0 = min(max(dp.x, 0), n - 1), s0 = min(max(sp.x, 0), n - 1);
        int d1 = min(max(dp.y, 0), n - 1), s1 = min(max(sp.y, 0), n - 1);
        int p0 = atomicAdd(&g_cursor[d0], 1);
        if (p0 < CAP) g_bucket[(size_t)d0 * CAP + p0] = s0;
        int p1 = atomicAdd(&g_cursor[d1], 1);
        if (p1 < CAP) g_bucket[(size_t)d1 * CAP + p1] = s1;
    }
}

// ---------------- x -> bf16 hi/lo planes ----------------
__global__ void k_split_x(const float* __restrict__ x, int total64) {
    int i = blockIdx.x * blockDim.x + threadIdx.x;
    if (i < total64) {
        float2 v = ((const float2*)x)[i];
        g_xh[i] = pack_bf2(v.x, v.y);
        g_xl[i] = pack_bf2(bf_res(v.x), bf_res(v.y));
    }
}

// ---------------- weight prep: transpose + bf16 hi/lo split ----------------
__global__ void k_prep_w(const float* __restrict__ Wl1, const float* __restrict__ Wr1,
                         const float* __restrict__ Wl2, const float* __restrict__ Wr2) {
    int idx = blockIdx.x * blockDim.x + threadIdx.x;    // 0..65535
    int l = idx >> 15;
    int r = idx & 32767;
    int k = r >> 7, nn = r & 127;
    const float* Wl = l ? Wl2 : Wl1;
    const float* Wr = l ? Wr2 : Wr1;
    float v = (k < 128) ? Wl[k * 128 + nn] : Wr[(k - 128) * 128 + nn];
    int chunk = k >> 5, kk = k & 31;
    g_Bh[l][chunk][nn * 32 + kk] = __float2bfloat16(v);
    g_Bl[l][chunk][nn * 32 + kk] = __float2bfloat16(bf_res(v));
}

// ---------------- mean aggregation: warp per node, hi-plane gather --------
// packed f32x2 accumulation with MASKED hi extraction (rel_err 5.26e-4,
// 2x margin under gate). 8-edge unroll; block=128. At its latency floor.
__global__ __launch_bounds__(128) void k_agg(int n, int sel) {
    const uint32_t* __restrict__ fh = sel ? g_hh : g_xh;
    int gw = (blockIdx.x * blockDim.x + threadIdx.x) >> 5;
    int lane = threadIdx.x & 31;
    if (gw >= n) return;
    int deg = min(g_cursor[gw], CAP);
    float inv = 1.0f / (float)max(deg, 1);
    const int* __restrict__ bk = &g_bucket[(size_t)gw * CAP];
    uint64_t acc01 = 0, acc23 = 0;     // packed fp32 pairs
    int e = 0;
    for (; e + 8 <= deg; e += 8) {
        int4 sa = *(const int4*)&bk[e];
        int4 sb = *(const int4*)&bk[e + 4];
        uint2 u0 = *(const uint2*)&fh[(size_t)sa.x * 64 + lane * 2];
        uint2 u1 = *(const uint2*)&fh[(size_t)sa.y * 64 + lane * 2];
        uint2 u2 = *(const uint2*)&fh[(size_t)sa.z * 64 + lane * 2];
        uint2 u3 = *(const uint2*)&fh[(size_t)sa.w * 64 + lane * 2];
        uint2 u4 = *(const uint2*)&fh[(size_t)sb.x * 64 + lane * 2];
        uint2 u5 = *(const uint2*)&fh[(size_t)sb.y * 64 + lane * 2];
        uint2 u6 = *(const uint2*)&fh[(size_t)sb.z * 64 + lane * 2];
        uint2 u7 = *(const uint2*)&fh[(size_t)sb.w * 64 + lane * 2];
        fadd2(acc01, u0.x << 16, u0.x & 0xFFFF0000u);
        fadd2(acc23, u0.y << 16, u0.y & 0xFFFF0000u);
        fadd2(acc01, u1.x << 16, u1.x & 0xFFFF0000u);
        fadd2(acc23, u1.y << 16, u1.y & 0xFFFF0000u);
        fadd2(acc01, u2.x << 16, u2.x & 0xFFFF0000u);
        fadd2(acc23, u2.y << 16, u2.y & 0xFFFF0000u);
        fadd2(acc01, u3.x << 16, u3.x & 0xFFFF0000u);
        fadd2(acc23, u3.y << 16, u3.y & 0xFFFF0000u);
        fadd2(acc01, u4.x << 16, u4.x & 0xFFFF0000u);
        fadd2(acc23, u4.y << 16, u4.y & 0xFFFF0000u);
        fadd2(acc01, u5.x << 16, u5.x & 0xFFFF0000u);
        fadd2(acc23, u5.y << 16, u5.y & 0xFFFF0000u);
        fadd2(acc01, u6.x << 16, u6.x & 0xFFFF0000u);
        fadd2(acc23, u6.y << 16, u6.y & 0xFFFF0000u);
        fadd2(acc01, u7.x << 16, u7.x & 0xFFFF0000u);
        fadd2(acc23, u7.y << 16, u7.y & 0xFFFF0000u);
    }
    for (; e < deg; e++) {
        uint2 u = *(const uint2*)&fh[(size_t)bk[e] * 64 + lane * 2];
        fadd2(acc01, u.x << 16, u.x & 0xFFFF0000u);
        fadd2(acc23, u.y << 16, u.y & 0xFFFF0000u);
    }
    float a0, a1, a2, a3;
    unpack2(acc01, a0, a1);
    unpack2(acc23, a2, a3);
    a0 *= inv; a1 *= inv; a2 *= inv; a3 *= inv;
    size_t w = (size_t)gw * 64 + lane * 2;
    g_ah[w]     = pack_bf2(a0, a1);
    g_ah[w + 1] = pack_bf2(a2, a3);
    g_al[w]     = pack_bf2(bf_res(a0), bf_res(a1));
    g_al[w + 1] = pack_bf2(bf_res(a2), bf_res(a3));
}

// ---------------- pipelined HMMA GEMM (3-stage, M128, single-sync loop) ----
// out[128 x 128] = [agg | self] @ B + bias; K=256 in 8 chunks of 32.
// dyn smem: 3 stages x (Ah 8K | Al 8K | Bh 8K | Bl 8K) + bias 512 = 98816 B
// (2 CTAs/SM: 193.2 KB < 228 KB smem)
#define STAGE_BYTES 32768
#define NSTAGE 3
#define SM_BIAS_OFF (NSTAGE * STAGE_BYTES)
#define SMEM_TOTAL  (SM_BIAS_OFF + 512)

__global__ __launch_bounds__(256, 2) void k_gemm(
        const float* __restrict__ bias, float* __restrict__ out,
        int n, int layer, int self_sel, int out_fp32, int do_relu) {
    extern __shared__ char smem[];
    uint32_t sb = smem_u32(smem);
    float* sbias = (float*)(smem + SM_BIAS_OFF);

    int tid = threadIdx.x, wid = tid >> 5, lid = tid & 31;
    int widm = wid & 3, widn = wid >> 2;
    int n0 = blockIdx.x * 128;
    if (tid < 128) sbias[tid] = bias[tid];

    const uint32_t* __restrict__ selfH = self_sel ? g_hh : g_xh;
    const uint32_t* __restrict__ selfL = self_sel ? g_hl : g_xl;

    int lA_row = lid & 15, lA_ci = lid >> 4;
    int lB_row = (lid & 7) + ((lid >> 4) << 3), lB_ci = (lid >> 3) & 1;

    float acc[2][8][4];
    #pragma unroll
    for (int mt = 0; mt < 2; mt++)
        #pragma unroll
        for (int nt = 0; nt < 8; nt++)
            #pragma unroll
            for (int j = 0; j < 4; j++) acc[mt][nt][j] = 0.f;

    auto issue = [&](int c, int st) {
        const uint32_t* pAh = (c < 4) ? g_ah : selfH;
        const uint32_t* pAl = (c < 4) ? g_al : selfL;
        const char* pBh = (const char*)&g_Bh[layer][c][0];
        const char* pBl = (const char*)&g_Bl[layer][c][0];
        uint32_t sa = sb + (uint32_t)st * STAGE_BYTES;
        int koff = (c & 3) * 16;   // u32 offset within 256B row
        #pragma unroll
        for (int g = 0; g < 2; g++) {
            int idx = tid + g * 256;          // 0..511
            int row = idx >> 2, ci = idx & 3;
            int gn = n0 + row;
            uint32_t ok = (gn < n) ? 16u : 0u;
            int gnc = (gn < n) ? gn : 0;
            const char* sh = (const char*)(pAh + (size_t)gnc * 64 + koff + ci * 4);
            const char* sl = (const char*)(pAl + (size_t)gnc * 64 + koff + ci * 4);
            uint32_t d0 = sa + SWZ(row, ci);
            cp16(d0,         sh, ok);
            cp16(d0 + 8192,  sl, ok);
            cp16(d0 + 16384, pBh + row * 64 + ci * 16, 16u);
            cp16(d0 + 24576, pBl + row * 64 + ci * 16, 16u);
        }
    };

    issue(0, 0); CP_COMMIT();
    issue(1, 1); CP_COMMIT();

    #pragma unroll 1
    for (int c = 0; c < 8; c++) {
        if (c < 7) { CP_WAIT(1); }   // stage c done (groups complete in order)
        else       { CP_WAIT(0); }   // last chunk: drain everything
        __syncthreads();             // all warps done computing stage (c-1)'s buffer
        if (c + 2 < 8) { issue(c + 2, (c + 2) % NSTAGE); CP_COMMIT(); }

        uint32_t base = sb + (uint32_t)(c % NSTAGE) * STAGE_BYTES;
        #pragma unroll
        for (int ks = 0; ks < 2; ks++) {
            int ciA = ks * 2 + lA_ci;
            uint32_t ah[2][4], al[2][4];
            #pragma unroll
            for (int mt = 0; mt < 2; mt++) {
                int row = widm * 32 + mt * 16 + lA_row;
                uint32_t off = SWZ(row, ciA);
                ldm_x4(ah[mt], base + off);
                ldm_x4(al[mt], base + 8192 + off);
            }
            int ciB = ks * 2 + lB_ci;
            uint32_t boff[4];
            uint32_t bf[4][4];
            #pragma unroll
            for (int g = 0; g < 4; g++) {
                int row = widn * 64 + g * 16 + lB_row;
                boff[g] = SWZ(row, ciB);
                ldm_x4(bf[g], base + 16384 + boff[g]);
            }
            #pragma unroll
            for (int mt = 0; mt < 2; mt++)
                #pragma unroll
                for (int g = 0; g < 4; g++) {
                    mma16816(acc[mt][2 * g],     ah[mt], bf[g][0], bf[g][1]);
                    mma16816(acc[mt][2 * g + 1], ah[mt], bf[g][2], bf[g][3]);
                    mma16816(acc[mt][2 * g],     al[mt], bf[g][0], bf[g][1]);
                    mma16816(acc[mt][2 * g + 1], al[mt], bf[g][2], bf[g][3]);
                }
            #pragma unroll
            for (int g = 0; g < 4; g++)
                ldm_x4(bf[g], base + 24576 + boff[g]);
            #pragma unroll
            for (int mt = 0; mt < 2; mt++)
                #pragma unroll
                for (int g = 0; g < 4; g++) {
                    mma16816(acc[mt][2 * g],     ah[mt], bf[g][0], bf[g][1]);
                    mma16816(acc[mt][2 * g + 1], ah[mt], bf[g][2], bf[g][3]);
                }
        }
    }

    // ---- epilogue ----
    int lr = lid >> 2, lc = (lid & 3) * 2;
    #pragma unroll
    for (int mt = 0; mt < 2; mt++) {
        #pragma unroll
        for (int pr = 0; pr < 2; pr++) {
            int gn = n0 + widm * 32 + mt * 16 + lr + pr * 8;
            if (gn >= n) continue;
            #pragma unroll
            for (int nt = 0; nt < 8; nt++) {
                int col = widn * 64 + nt * 8 + lc;
                float v0 = acc[mt][nt][pr * 2]     + sbias[col];
                float v1 = acc[mt][nt][pr * 2 + 1] + sbias[col + 1];
                if (do_relu) { v0 = fmaxf(v0, 0.f); v1 = fmaxf(v1, 0.f); }
                if (out_fp32) {
                    *(float2*)&out[(size_t)gn * D + col] = make_float2(v0, v1);
                } else {
                    size_t w = (size_t)gn * 64 + (col >> 1);
                    g_hh[w] = pack_bf2(v0, v1);
                    g_hl[w] = pack_bf2(bf_res(v0), bf_res(v1));
                }
            }
        }
    }
}

// ---------------- launch ----------------
extern "C" void kernel_launch(void* const* d_in, const int* in_sizes, int n_in,
                              void* d_out, int out_size) {
    const float* x   = (const float*)d_in[0];
    const int*   ei  = (const int*)d_in[1];     // int32 edge_index
    const float* W1l = (const float*)d_in[2];
    const float* b1  = (const float*)d_in[3];
    const float* W1r = (const float*)d_in[4];
    const float* W2l = (const float*)d_in[5];
    const float* b2  = (const float*)d_in[6];
    const float* W2r = (const float*)d_in[7];
    float* out = (float*)d_out;

    int n = in_sizes[0] / D;
    int E = in_sizes[1] / 2;

    static cudaStream_t sB = nullptr;
    static cudaEvent_t evFork, evJoin;
    static void* cursor_ptr = nullptr;
    if (!sB) {
        cudaFuncSetAttribute(k_gemm, cudaFuncAttributeMaxDynamicSharedMemorySize, SMEM_TOTAL);
        cudaStreamCreateWithFlags(&sB, cudaStreamNonBlocking);
        cudaEventCreateWithFlags(&evFork, cudaEventDisableTiming);
        cudaEventCreateWithFlags(&evJoin, cudaEventDisableTiming);
        cudaGetSymbolAddress(&cursor_ptr, g_cursor);
    }

    // fork: stream B does weight prep + x split while main stream builds graph
    cudaEventRecord(evFork, 0);
    cudaStreamWaitEvent(sB, evFork, 0);
    k_prep_w <<<256, 256, 0, sB>>>(W1l, W1r, W2l, W2r);
    k_split_x<<<(n * 64 + 255) / 256, 256, 0, sB>>>(x, n * 64);
    cudaEventRecord(evJoin, sB);

    cudaMemsetAsync(cursor_ptr, 0, (size_t)n * sizeof(int), 0);
    k_scatter<<<(E / 2 + 255) / 256, 256>>>(ei, E / 2, n);

    cudaStreamWaitEvent(0, evJoin, 0);   // join before layer 1

    int agg_blocks  = (n * 32 + 127) / 128;
    int gemm_blocks = (n + 127) / 128;

    // layer 1: h = relu(agg(x)@W1l + x@W1r + b1)  -> hi/lo planes
    k_agg <<<agg_blocks, 128>>>(n, 0);
    k_gemm<<<gemm_blocks, 256, SMEM_TOTAL>>>(b1, out, n, 0, /*self=x*/0, /*fp32*/0, /*relu*/1);

    // layer 2: out = agg(h)@W2l + h@W2r + b2  -> fp32 d_out
    k_agg <<<agg_blocks, 128>>>(n, 1);
    k_gemm<<<gemm_blocks, 256, SMEM_TOTAL>>>(b2, out, n, 1, /*self=h*/1, /*fp32*/1, /*relu*/0);
}

// round 17
// speedup vs baseline: 1.0264x; 1.0264x over previous
#include <cuda_runtime.h>
#include <cuda_bf16.h>
#include <cstdint>

// ---------------- problem constants ----------------
#define MAX_N 50000
#define MAX_E 800000
#define D 128
#define CAP 64          // bucket slots per node (deg ~ Poisson(16); P(>=64) ~ 2e-18)

// ---------------- device-global scratch ----------------
__device__ int g_cursor[MAX_N];
__device__ int g_bucket[(size_t)MAX_N * CAP];
// bf16 hi/lo feature planes, each [node][64] u32 (= 128 bf16 per row, 256B)
__device__ __align__(128) uint32_t g_xh[(size_t)MAX_N * 64];
__device__ __align__(128) uint32_t g_xl[(size_t)MAX_N * 64];
__device__ __align__(128) uint32_t g_ah[(size_t)MAX_N * 64];
__device__ __align__(128) uint32_t g_al[(size_t)MAX_N * 64];
__device__ __align__(128) uint32_t g_hh[(size_t)MAX_N * 64];
__device__ __align__(128) uint32_t g_hl[(size_t)MAX_N * 64];
// bf16 hi/lo weight images, transposed: [layer][chunk(8)][n=128][k=32]
__device__ __align__(128) __nv_bfloat16 g_Bh[2][8][128 * 32];
__device__ __align__(128) __nv_bfloat16 g_Bl[2][8][128 * 32];

// ---------------- small helpers ----------------
__device__ __forceinline__ uint32_t pack_bf2(float a, float b) {
    __nv_bfloat162 t;
    t.x = __float2bfloat16(a);
    t.y = __float2bfloat16(b);
    return *reinterpret_cast<uint32_t*>(&t);
}
__device__ __forceinline__ float bf_res(float v) {
    return v - __bfloat162float(__float2bfloat16(v));
}
// packed f32x2 accumulate: acc += {lo_bits, hi_bits} viewed as 2 floats
__device__ __forceinline__ void fadd2(uint64_t& acc, uint32_t f0, uint32_t f1) {
    uint64_t v;
    asm("mov.b64 %0, {%1, %2};" : "=l"(v) : "r"(f0), "r"(f1));
    asm("add.rn.f32x2 %0, %0, %1;" : "+l"(acc) : "l"(v));
}
__device__ __forceinline__ void fadd2m(uint64_t& acc, uint64_t v) {
    asm("add.rn.f32x2 %0, %0, %1;" : "+l"(acc) : "l"(v));
}
__device__ __forceinline__ void unpack2(uint64_t acc, float& a, float& b) {
    uint32_t u0, u1;
    asm("mov.b64 {%0, %1}, %2;" : "=r"(u0), "=r"(u1) : "l"(acc));
    a = __uint_as_float(u0);
    b = __uint_as_float(u1);
}

__device__ __forceinline__ uint32_t smem_u32(const void* p) {
    uint32_t a;
    asm("{ .reg .u64 t; cvta.to.shared.u64 t, %1; cvt.u32.u64 %0, t; }" : "=r"(a) : "l"(p));
    return a;
}
__device__ __forceinline__ void ldm_x4(uint32_t* r, uint32_t addr) {
    asm volatile("ldmatrix.sync.aligned.m8n8.x4.shared.b16 {%0,%1,%2,%3}, [%4];"
                 : "=r"(r[0]), "=r"(r[1]), "=r"(r[2]), "=r"(r[3]) : "r"(addr));
}
__device__ __forceinline__ void mma16816(float* d, const uint32_t* a, uint32_t b0, uint32_t b1) {
    asm volatile("mma.sync.aligned.m16n8k16.row.col.f32.bf16.bf16.f32 "
                 "{%0,%1,%2,%3}, {%4,%5,%6,%7}, {%8,%9}, {%0,%1,%2,%3};"
                 : "+f"(d[0]), "+f"(d[1]), "+f"(d[2]), "+f"(d[3])
                 : "r"(a[0]), "r"(a[1]), "r"(a[2]), "r"(a[3]), "r"(b0), "r"(b1));
}
__device__ __forceinline__ void cp16(uint32_t dst, const void* src, uint32_t sz) {
    asm volatile("cp.async.cg.shared.global [%0], [%1], 16, %2;"
                 :: "r"(dst), "l"(src), "r"(sz) : "memory");
}
#define CP_COMMIT()  asm volatile("cp.async.commit_group;" ::: "memory")
#define CP_WAIT(N)   asm volatile("cp.async.wait_group %0;" :: "n"(N) : "memory")

// XOR swizzle: 64B rows, 4x16B chunks; conflict-free for ldmatrix
#define SWZ(row, ci) (((uint32_t)(row) << 6) + (((((ci) ^ ((row) >> 1)) & 3)) << 4))

// ---------------- graph build: single-pass bucket scatter ----------------
__global__ void k_scatter(const int* __restrict__ ei, int E2, int n) {
    int t = blockIdx.x * blockDim.x + threadIdx.x;   // handles 2 edges
    if (t < E2) {
        int2 sp = ((const int2*)ei)[t];
        int2 dp = ((const int2*)(ei + 2 * E2))[t];
        int d0 = min(max(dp.x, 0), n - 1), s0 = min(max(sp.x, 0), n - 1);
        int d1 = min(max(dp.y, 0), n - 1), s1 = min(max(sp.y, 0), n - 1);
        int p0 = atomicAdd(&g_cursor[d0], 1);
        if (p0 < CAP) g_bucket[(size_t)d0 * CAP + p0] = s0;
        int p1 = atomicAdd(&g_cursor[d1], 1);
        if (p1 < CAP) g_bucket[(size_t)d1 * CAP + p1] = s1;
    }
}

// ---------------- x -> bf16 hi/lo planes ----------------
__global__ void k_split_x(const float* __restrict__ x, int total64) {
    int i = blockIdx.x * blockDim.x + threadIdx.x;
    if (i < total64) {
        float2 v = ((const float2*)x)[i];
        g_xh[i] = pack_bf2(v.x, v.y);
        g_xl[i] = pack_bf2(bf_res(v.x), bf_res(v.y));
    }
}

// ---------------- weight prep: transpose + bf16 hi/lo split ----------------
__global__ void k_prep_w(const float* __restrict__ Wl1, const float* __restrict__ Wr1,
                         const float* __restrict__ Wl2, const float* __restrict__ Wr2) {
    int idx = blockIdx.x * blockDim.x + threadIdx.x;    // 0..65535
    int l = idx >> 15;
    int r = idx & 32767;
    int k = r >> 7, nn = r & 127;
    const float* Wl = l ? Wl2 : Wl1;
    const float* Wr = l ? Wr2 : Wr1;
    float v = (k < 128) ? Wl[k * 128 + nn] : Wr[(k - 128) * 128 + nn];
    int chunk = k >> 5, kk = k & 31;
    g_Bh[l][chunk][nn * 32 + kk] = __float2bfloat16(v);
    g_Bl[l][chunk][nn * 32 + kk] = __float2bfloat16(bf_res(v));
}

// ---------------- mean aggregation: warp per node, hi-plane gather --------
// packed f32x2 accumulation, 4 independent chains (halved FADD dependency
// depth); masked hi extraction; 8-edge unroll; block=128.
__global__ __launch_bounds__(128) void k_agg(int n, int sel) {
    const uint32_t* __restrict__ fh = sel ? g_hh : g_xh;
    int gw = (blockIdx.x * blockDim.x + threadIdx.x) >> 5;
    int lane = threadIdx.x & 31;
    if (gw >= n) return;
    int deg = min(g_cursor[gw], CAP);
    float inv = 1.0f / (float)max(deg, 1);
    const int* __restrict__ bk = &g_bucket[(size_t)gw * CAP];
    uint64_t acc01a = 0, acc23a = 0;   // chain A (even edges)
    uint64_t acc01b = 0, acc23b = 0;   // chain B (odd edges)
    int e = 0;
    for (; e + 8 <= deg; e += 8) {
        int4 sa = *(const int4*)&bk[e];
        int4 sb = *(const int4*)&bk[e + 4];
        uint2 u0 = *(const uint2*)&fh[(size_t)sa.x * 64 + lane * 2];
        uint2 u1 = *(const uint2*)&fh[(size_t)sa.y * 64 + lane * 2];
        uint2 u2 = *(const uint2*)&fh[(size_t)sa.z * 64 + lane * 2];
        uint2 u3 = *(const uint2*)&fh[(size_t)sa.w * 64 + lane * 2];
        uint2 u4 = *(const uint2*)&fh[(size_t)sb.x * 64 + lane * 2];
        uint2 u5 = *(const uint2*)&fh[(size_t)sb.y * 64 + lane * 2];
        uint2 u6 = *(const uint2*)&fh[(size_t)sb.z * 64 + lane * 2];
        uint2 u7 = *(const uint2*)&fh[(size_t)sb.w * 64 + lane * 2];
        fadd2(acc01a, u0.x << 16, u0.x & 0xFFFF0000u);
        fadd2(acc23a, u0.y << 16, u0.y & 0xFFFF0000u);
        fadd2(acc01b, u1.x << 16, u1.x & 0xFFFF0000u);
        fadd2(acc23b, u1.y << 16, u1.y & 0xFFFF0000u);
        fadd2(acc01a, u2.x << 16, u2.x & 0xFFFF0000u);
        fadd2(acc23a, u2.y << 16, u2.y & 0xFFFF0000u);
        fadd2(acc01b, u3.x << 16, u3.x & 0xFFFF0000u);
        fadd2(acc23b, u3.y << 16, u3.y & 0xFFFF0000u);
        fadd2(acc01a, u4.x << 16, u4.x & 0xFFFF0000u);
        fadd2(acc23a, u4.y << 16, u4.y & 0xFFFF0000u);
        fadd2(acc01b, u5.x << 16, u5.x & 0xFFFF0000u);
        fadd2(acc23b, u5.y << 16, u5.y & 0xFFFF0000u);
        fadd2(acc01a, u6.x << 16, u6.x & 0xFFFF0000u);
        fadd2(acc23a, u6.y << 16, u6.y & 0xFFFF0000u);
        fadd2(acc01b, u7.x << 16, u7.x & 0xFFFF0000u);
        fadd2(acc23b, u7.y << 16, u7.y & 0xFFFF0000u);
    }
    for (; e < deg; e++) {
        uint2 u = *(const uint2*)&fh[(size_t)bk[e] * 64 + lane * 2];
        fadd2(acc01a, u.x << 16, u.x & 0xFFFF0000u);
        fadd2(acc23a, u.y << 16, u.y & 0xFFFF0000u);
    }
    fadd2m(acc01a, acc01b);
    fadd2m(acc23a, acc23b);
    float a0, a1, a2, a3;
    unpack2(acc01a, a0, a1);
    unpack2(acc23a, a2, a3);
    a0 *= inv; a1 *= inv; a2 *= inv; a3 *= inv;
    size_t w = (size_t)gw * 64 + lane * 2;
    g_ah[w]     = pack_bf2(a0, a1);
    g_ah[w + 1] = pack_bf2(a2, a3);
    g_al[w]     = pack_bf2(bf_res(a0), bf_res(a1));
    g_al[w + 1] = pack_bf2(bf_res(a2), bf_res(a3));
}

// ---------------- pipelined HMMA GEMM (2-stage, M128, single-sync loop) ----
// out[128 x 128] = [agg | self] @ B + bias; K=256 in 8 chunks of 32.
// dyn smem: 2 stages x (Ah 8K | Al 8K | Bh 8K | Bl 8K) + bias 512 = 66048 B
#define STAGE_BYTES 32768
#define SM_BIAS_OFF 65536
#define SMEM_TOTAL  66048

__global__ __launch_bounds__(256, 2) void k_gemm(
        const float* __restrict__ bias, float* __restrict__ out,
        int n, int layer, int self_sel, int out_fp32, int do_relu) {
    extern __shared__ char smem[];
    uint32_t sb = smem_u32(smem);
    float* sbias = (float*)(smem + SM_BIAS_OFF);

    int tid = threadIdx.x, wid = tid >> 5, lid = tid & 31;
    int widm = wid & 3, widn = wid >> 2;
    int n0 = blockIdx.x * 128;
    if (tid < 128) sbias[tid] = bias[tid];

    const uint32_t* __restrict__ selfH = self_sel ? g_hh : g_xh;
    const uint32_t* __restrict__ selfL = self_sel ? g_hl : g_xl;

    int lA_row = lid & 15, lA_ci = lid >> 4;
    int lB_row = (lid & 7) + ((lid >> 4) << 3), lB_ci = (lid >> 3) & 1;

    float acc[2][8][4];
    #pragma unroll
    for (int mt = 0; mt < 2; mt++)
        #pragma unroll
        for (int nt = 0; nt < 8; nt++)
            #pragma unroll
            for (int j = 0; j < 4; j++) acc[mt][nt][j] = 0.f;

    auto issue = [&](int c, int st) {
        const uint32_t* pAh = (c < 4) ? g_ah : selfH;
        const uint32_t* pAl = (c < 4) ? g_al : selfL;
        const char* pBh = (const char*)&g_Bh[layer][c][0];
        const char* pBl = (const char*)&g_Bl[layer][c][0];
        uint32_t sa = sb + st * STAGE_BYTES;
        int koff = (c & 3) * 16;   // u32 offset within 256B row
        #pragma unroll
        for (int g = 0; g < 2; g++) {
            int idx = tid + g * 256;          // 0..511
            int row = idx >> 2, ci = idx & 3;
            int gn = n0 + row;
            uint32_t ok = (gn < n) ? 16u : 0u;
            int gnc = (gn < n) ? gn : 0;
            const char* sh = (const char*)(pAh + (size_t)gnc * 64 + koff + ci * 4);
            const char* sl = (const char*)(pAl + (size_t)gnc * 64 + koff + ci * 4);
            uint32_t d0 = sa + SWZ(row, ci);
            cp16(d0,         sh, ok);
            cp16(d0 + 8192,  sl, ok);
            cp16(d0 + 16384, pBh + row * 64 + ci * 16, 16u);
            cp16(d0 + 24576, pBl + row * 64 + ci * 16, 16u);
        }
    };

    issue(0, 0);
    CP_COMMIT();

    #pragma unroll 1
    for (int c = 0; c < 8; c++) {
        CP_WAIT(0);            // stage c complete (only group outstanding)
        __syncthreads();       // visible to all warps; all done with stage c^1
        if (c < 7) { issue(c + 1, (c + 1) & 1); CP_COMMIT(); }

        uint32_t base = sb + (c & 1) * STAGE_BYTES;
        #pragma unroll
        for (int ks = 0; ks < 2; ks++) {
            int ciA = ks * 2 + lA_ci;
            uint32_t ah[2][4], al[2][4];
            #pragma unroll
            for (int mt = 0; mt < 2; mt++) {
                int row = widm * 32 + mt * 16 + lA_row;
                uint32_t off = SWZ(row, ciA);
                ldm_x4(ah[mt], base + off);
                ldm_x4(al[mt], base + 8192 + off);
            }
            int ciB = ks * 2 + lB_ci;
            uint32_t boff[4];
            uint32_t bf[4][4];
            #pragma unroll
            for (int g = 0; g < 4; g++) {
                int row = widn * 64 + g * 16 + lB_row;
                boff[g] = SWZ(row, ciB);
                ldm_x4(bf[g], base + 16384 + boff[g]);
            }
            #pragma unroll
            for (int mt = 0; mt < 2; mt++)
                #pragma unroll
                for (int g = 0; g < 4; g++) {
                    mma16816(acc[mt][2 * g],     ah[mt], bf[g][0], bf[g][1]);
                    mma16816(acc[mt][2 * g + 1], ah[mt], bf[g][2], bf[g][3]);
                    mma16816(acc[mt][2 * g],     al[mt], bf[g][0], bf[g][1]);
                    mma16816(acc[mt][2 * g + 1], al[mt], bf[g][2], bf[g][3]);
                }
            #pragma unroll
            for (int g = 0; g < 4; g++)
                ldm_x4(bf[g], base + 24576 + boff[g]);
            #pragma unroll
            for (int mt = 0; mt < 2; mt++)
                #pragma unroll
                for (int g = 0; g < 4; g++) {
                    mma16816(acc[mt][2 * g],     ah[mt], bf[g][0], bf[g][1]);
                    mma16816(acc[mt][2 * g + 1], ah[mt], bf[g][2], bf[g][3]);
                }
        }
    }

    // ---- epilogue ----
    int lr = lid >> 2, lc = (lid & 3) * 2;
    #pragma unroll
    for (int mt = 0; mt < 2; mt++) {
        #pragma unroll
        for (int pr = 0; pr < 2; pr++) {
            int gn = n0 + widm * 32 + mt * 16 + lr + pr * 8;
            if (gn >= n) continue;
            #pragma unroll
            for (int nt = 0; nt < 8; nt++) {
                int col = widn * 64 + nt * 8 + lc;
                float v0 = acc[mt][nt][pr * 2]     + sbias[col];
                float v1 = acc[mt][nt][pr * 2 + 1] + sbias[col + 1];
                if (do_relu) { v0 = fmaxf(v0, 0.f); v1 = fmaxf(v1, 0.f); }
                if (out_fp32) {
                    *(float2*)&out[(size_t)gn * D + col] = make_float2(v0, v1);
                } else {
                    size_t w = (size_t)gn * 64 + (col >> 1);
                    g_hh[w] = pack_bf2(v0, v1);
                    g_hl[w] = pack_bf2(bf_res(v0), bf_res(v1));
                }
            }
        }
    }
}

// ---------------- launch ----------------
extern "C" void kernel_launch(void* const* d_in, const int* in_sizes, int n_in,
                              void* d_out, int out_size) {
    const float* x   = (const float*)d_in[0];
    const int*   ei  = (const int*)d_in[1];     // int32 edge_index
    const float* W1l = (const float*)d_in[2];
    const float* b1  = (const float*)d_in[3];
    const float* W1r = (const float*)d_in[4];
    const float* W2l = (const float*)d_in[5];
    const float* b2  = (const float*)d_in[6];
    const float* W2r = (const float*)d_in[7];
    float* out = (float*)d_out;

    int n = in_sizes[0] / D;
    int E = in_sizes[1] / 2;

    static cudaStream_t sB = nullptr;
    static cudaEvent_t evFork, evJoin;
    static void* cursor_ptr = nullptr;
    if (!sB) {
        cudaFuncSetAttribute(k_gemm, cudaFuncAttributeMaxDynamicSharedMemorySize, SMEM_TOTAL);
        cudaStreamCreateWithFlags(&sB, cudaStreamNonBlocking);
        cudaEventCreateWithFlags(&evFork, cudaEventDisableTiming);
        cudaEventCreateWithFlags(&evJoin, cudaEventDisableTiming);
        cudaGetSymbolAddress(&cursor_ptr, g_cursor);
    }

    // fork: stream B does weight prep + x split while main stream builds graph
    cudaEventRecord(evFork, 0);
    cudaStreamWaitEvent(sB, evFork, 0);
    k_prep_w <<<256, 256, 0, sB>>>(W1l, W1r, W2l, W2r);
    k_split_x<<<(n * 64 + 255) / 256, 256, 0, sB>>>(x, n * 64);
    cudaEventRecord(evJoin, sB);

    cudaMemsetAsync(cursor_ptr, 0, (size_t)n * sizeof(int), 0);
    k_scatter<<<(E / 2 + 255) / 256, 256>>>(ei, E / 2, n);

    cudaStreamWaitEvent(0, evJoin, 0);   // join before layer 1

    int agg_blocks  = (n * 32 + 127) / 128;
    int gemm_blocks = (n + 127) / 128;

    // layer 1: h = relu(agg(x)@W1l + x@W1r + b1)  -> hi/lo planes
    k_agg <<<agg_blocks, 128>>>(n, 0);
    k_gemm<<<gemm_blocks, 256, SMEM_TOTAL>>>(b1, out, n, 0, /*self=x*/0, /*fp32*/0, /*relu*/1);

    // layer 2: out = agg(h)@W2l + h@W2r + b2  -> fp32 d_out
    k_agg <<<agg_blocks, 128>>>(n, 1);
    k_gemm<<<gemm_blocks, 256, SMEM_TOTAL>>>(b2, out, n, 1, /*self=h*/1, /*fp32*/1, /*relu*/0);
}